// round 14
// baseline (speedup 1.0000x reference)
#include <cuda_runtime.h>
#include <cuda_bf16.h>
#include <math.h>

#define NBLK 128
#define NTHR 512
#define Bn 64
#define Sn 512
#define BH 32768

typedef unsigned u32;
typedef unsigned long long u64;

// output section offsets (floats)
#define O_HID   0ull
#define O_HMU   16777216ull
#define O_HSTD  33587200ull
#define O_CMU   50397184ull
#define O_CSTD  67207168ull
#define O_HT    84017152ull
#define O_CT    84049920ull

// global state
__device__ __nv_bfloat16 g_xh[(size_t)Bn*Sn*512];   // [b][s][k]
__device__ __nv_bfloat16 g_xl[(size_t)Bn*Sn*512];
__device__ __nv_bfloat16 g_hh[2*BH], g_hl[2*BH];    // sampled h, parity-buffered
__device__ float g_cs[2*BH];                        // sampled c, parity-buffered
__device__ __nv_bfloat16 g_nhh[BH], g_nhl[BH];      // h_new (single buffer)
__device__ __nv_bfloat16 g_nch[BH], g_ncl[BH];      // c_new
__device__ float g_x1[(size_t)Sn*128*1024];         // precomputed x-gates [s][cb][c][b]
__device__ int g_flag[128*32];
__device__ int g_rel;
__device__ int g_cnt1[4];                           // per-chunk handoff counters (monotonic)

// flag-array grid barrier, replay-safe (gen seeded from g_rel at kernel entry)
__device__ __forceinline__ void grid_bar(int& gen) {
    __syncthreads();
    ++gen;
    if (threadIdx.x == 0) {
        __threadfence();
        *(volatile int*)&g_flag[blockIdx.x * 32] = gen;
    }
    if (blockIdx.x == 0) {
        if (threadIdx.x < 128)
            while (*(volatile int*)&g_flag[threadIdx.x * 32] < gen) { }
        __syncthreads();
        if (threadIdx.x == 0) { __threadfence(); *(volatile int*)&g_rel = gen; }
    }
    if (threadIdx.x == 0) {
        while (*(volatile int*)&g_rel < gen) { }
        __threadfence();
    }
    __syncthreads();
}

__device__ __forceinline__ float sigm(float v) { return 1.0f / (1.0f + expf(-v)); }
__device__ __forceinline__ float softplus(float v) {
    return fmaxf(v, 0.0f) + log1pf(expf(-fabsf(v)));
}

// ---------- PTX helpers (sm_80+, legal on compute_100) ----------
__device__ __forceinline__ u32 smem_u32(const void* p) {
    u32 a;
    asm("{ .reg .u64 t; cvta.to.shared.u64 t, %1; cvt.u32.u64 %0, t; }" : "=r"(a) : "l"(p));
    return a;
}
__device__ __forceinline__ void cpa16(u32 dst, const void* src) {
    asm volatile("cp.async.cg.shared.global [%0], [%1], 16;" :: "r"(dst), "l"(src));
}
__device__ __forceinline__ void cpa_commit() {
    asm volatile("cp.async.commit_group;" ::: "memory");
}
template <int N> __device__ __forceinline__ void cpa_wait() {
    asm volatile("cp.async.wait_group %0;" :: "n"(N) : "memory");
}
__device__ __forceinline__ void ldm4(u32* r, u32 addr) {
    asm volatile("ldmatrix.sync.aligned.m8n8.x4.shared.b16 {%0,%1,%2,%3}, [%4];"
                 : "=r"(r[0]), "=r"(r[1]), "=r"(r[2]), "=r"(r[3]) : "r"(addr));
}
__device__ __forceinline__ void lds2(u32& x, u32& y, u32 a) {
    asm volatile("ld.shared.v2.b32 {%0,%1}, [%2];" : "=r"(x), "=r"(y) : "r"(a));
}
__device__ __forceinline__ void mma16816(float* d, const u32* a, u32 b0, u32 b1) {
    asm volatile(
        "mma.sync.aligned.m16n8k16.row.col.f32.bf16.bf16.f32 "
        "{%0,%1,%2,%3}, {%4,%5,%6,%7}, {%8,%9}, {%0,%1,%2,%3};"
        : "+f"(d[0]), "+f"(d[1]), "+f"(d[2]), "+f"(d[3])
        : "r"(a[0]), "r"(a[1]), "r"(a[2]), "r"(a[3]), "r"(b0), "r"(b1));
}
__device__ __forceinline__ u32 hpair(__nv_bfloat16 a, __nv_bfloat16 b) {
    unsigned short ua = *(unsigned short*)&a, ub = *(unsigned short*)&b;
    return (u32)ua | ((u32)ub << 16);
}

#define ABUF 34816      // per buffer: hi [64][272B] + lo at +17408
#define AST  272

// main-kernel SMEM map (bytes)
#define SO_W1H  0
#define SO_W1L  16384
#define SO_W2H  32768
#define SO_W2L  49152
#define SO_A    65536      // 3 x 34816
#define SO_DP   169984     // 4 x 64 x 18 f32
#define SO_B1   188416
#define SMEM_BYTES 188480

// precomp-kernel SMEM map
#define SP_WXH  0
#define SP_WXL  16384
#define SP_A    32768      // 3 x 34816
#define SP_DP   137216
#define SMEM_P  155648

// one-time x split
__global__ void xsplit_kernel(const float* __restrict__ x) {
    size_t i = (size_t)blockIdx.x * 256 + threadIdx.x;
    float v = x[i];
    __nv_bfloat16 hi = __float2bfloat16(v);
    g_xh[i] = hi;
    g_xl[i] = __float2bfloat16(v - __bfloat162float(hi));
}

// ---------------- precompute: X1[s][cb] = x_s @ W_ih^T (16 cols per cb) ----------------
__global__ __launch_bounds__(512, 1)
void precomp(const float* __restrict__ W_ih) {
    extern __shared__ char smem8[];
    float* Dp = (float*)(smem8 + SP_DP);

    const int tid  = threadIdx.x;
    const int wid  = tid >> 5;
    const int lane = tid & 31;
    const int cb   = blockIdx.x;
    const int sblk = blockIdx.y;
    const int n0_1 = cb << 2;

    const u32 sb  = smem_u32(smem8);
    const u32 sbA = sb + SP_A;

    const int mt    = wid & 3;
    const int khalf = wid >> 2;
    const u32 aRow  = (u32)((mt * 16 + (lane & 7) + ((lane >> 3) & 1) * 8) * AST);
    const u32 aColH = (u32)(((lane >> 4) & 1) * 16);
    const int lrow  = tid >> 3;
    const u32 lq32  = (u32)((tid & 7) << 5);

    for (int i = tid; i < 2048; i += 512) {
        int fr = i >> 5, l = i & 31;
        int ktg = fr >> 1, ntw = fr & 1;
        int nl = ntw * 8 + (l >> 2);
        int gcol = (nl >> 2) * 512 + n0_1 + (nl & 3);
        int k0 = ktg * 16 + 2 * (l & 3);
        const float* base = W_ih + gcol * 512;
        float w00 = base[k0], w01 = base[k0 + 1], w08 = base[k0 + 8], w09 = base[k0 + 9];
        __nv_bfloat16 h00 = __float2bfloat16(w00), h01 = __float2bfloat16(w01);
        __nv_bfloat16 h08 = __float2bfloat16(w08), h09 = __float2bfloat16(w09);
        u32 off = (u32)(fr * 256 + l * 8);
        *(u32*)(smem8 + SP_WXH + off)     = hpair(h00, h01);
        *(u32*)(smem8 + SP_WXH + off + 4) = hpair(h08, h09);
        *(u32*)(smem8 + SP_WXL + off)     = hpair(__float2bfloat16(w00 - __bfloat162float(h00)),
                                                  __float2bfloat16(w01 - __bfloat162float(h01)));
        *(u32*)(smem8 + SP_WXL + off + 4) = hpair(__float2bfloat16(w08 - __bfloat162float(h08)),
                                                  __float2bfloat16(w09 - __bfloat162float(h09)));
    }
    __syncthreads();

    auto issueP = [&](int gc) {
        int s_ = sblk * 64 + (gc >> 2);
        int c_ = gc & 3;
        size_t o = ((size_t)lrow * Sn + s_) * 512 + (size_t)c_ * 128;
        u32 d = sbA + (u32)((gc % 3) * ABUF) + (u32)(lrow * AST) + lq32;
        const char* gh = (const char*)(g_xh + o) + lq32;
        const char* gl = (const char*)(g_xl + o) + lq32;
        cpa16(d,              gh);
        cpa16(d + 16,         gh + 16);
        cpa16(d + 17408,      gl);
        cpa16(d + 17408 + 16, gl + 16);
        cpa_commit();
    };

    float acc[16];
    auto compute = [&](int bf, u32 wH, u32 wL, int ktgBase) {
        u32 ab = sbA + (u32)(bf * ABUF) + aRow + aColH + (u32)(khalf * 64);
        #pragma unroll
        for (int kt = 0; kt < 2; ++kt) {
            u32 ah[4], al[4];
            ldm4(ah, ab + kt * 32);
            ldm4(al, ab + kt * 32 + 17408);
            u32 wb = (u32)((ktgBase + kt) * 512 + lane * 8);
            u32 h0a, h0b, h1a, h1b, l0a, l0b, l1a, l1b;
            lds2(h0a, h0b, wH + wb);
            lds2(h1a, h1b, wH + wb + 256);
            lds2(l0a, l0b, wL + wb);
            lds2(l1a, l1b, wL + wb + 256);
            float* A0 = acc + kt * 8;
            float* A1 = A0 + 4;
            mma16816(A0, ah, h0a, h0b);
            mma16816(A1, ah, h1a, h1b);
            mma16816(A0, ah, l0a, l0b);
            mma16816(A1, ah, l1a, l1b);
            mma16816(A0, al, h0a, h0b);
            mma16816(A1, al, h1a, h1b);
        }
    };
    auto storeDp = [&]() {
        int rlo = mt * 16 + (lane >> 2);
        int cc  = 2 * (lane & 3);
        float* dp = Dp + khalf * 1152;
        #pragma unroll
        for (int nt = 0; nt < 2; ++nt) {
            float* A = acc + nt * 4;
            int c = nt * 8 + cc;
            dp[rlo * 18 + c]           = A[0] + A[8];
            dp[rlo * 18 + c + 1]       = A[1] + A[9];
            dp[(rlo + 8) * 18 + c]     = A[2] + A[10];
            dp[(rlo + 8) * 18 + c + 1] = A[3] + A[11];
        }
    };

    const int e_b  = tid & 63;
    const int e_nn = (tid >> 6) & 3;

    issueP(0); issueP(1);
    for (int sl = 0; sl < 64; ++sl) {
        #pragma unroll
        for (int i = 0; i < 16; ++i) acc[i] = 0.f;
        #pragma unroll
        for (int c = 0; c < 4; ++c) {
            int gc = sl * 4 + c;
            if (gc == 255) cpa_wait<0>(); else cpa_wait<1>();
            __syncthreads();
            compute(gc % 3, sb + SP_WXH, sb + SP_WXL, c * 8 + khalf * 2);
            if (gc + 2 < 256) issueP(gc + 2);
        }
        storeDp();
        __syncthreads();
        if (tid < 256) {
            int s_ = sblk * 64 + sl;
            float* dst = g_x1 + ((size_t)s_ * 128 + cb) * 1024;
            #pragma unroll
            for (int gg = 0; gg < 4; ++gg) {
                int c2 = gg * 4 + e_nn;
                float v = 0.f;
                #pragma unroll
                for (int kp = 0; kp < 4; ++kp) v += Dp[kp * 1152 + e_b * 18 + c2];
                dst[c2 * 64 + e_b] = v;
            }
        }
        __syncthreads();
    }
}

// ---------------- main persistent kernel ----------------
__global__ __launch_bounds__(NTHR, 1)
void rglstm(const float* __restrict__ W_ih, const float* __restrict__ W_hh,
            const float* __restrict__ b_ih, const float* __restrict__ b_hh,
            const float* __restrict__ W_hg, const float* __restrict__ W_cg,
            const float* __restrict__ eps_h, const float* __restrict__ eps_c,
            float* __restrict__ out)
{
    extern __shared__ char smem8[];
    float* sB1 = (float*)(smem8 + SO_B1);
    float* Dp  = (float*)(smem8 + SO_DP);     // [4][64][18]

    const int tid  = threadIdx.x;
    const int wid  = tid >> 5;
    const int lane = tid & 31;
    const int cb   = blockIdx.x;
    const bool isH = cb < 64;
    const int n0_1 = cb << 2;
    const int n0_2 = (cb & 63) << 3;

    const u32 sb  = smem_u32(smem8);
    const u32 sbA = sb + SO_A;

    const int mt    = wid & 3;
    const int khalf = wid >> 2;
    const u32 aRow  = (u32)((mt * 16 + (lane & 7) + ((lane >> 3) & 1) * 8) * AST);
    const u32 aColH = (u32)(((lane >> 4) & 1) * 16);
    const int lrow  = tid >> 3;
    const u32 lq32  = (u32)((tid & 7) << 5);

    int gen = *(volatile int*)&g_rel;         // replay-safe barrier seed

    // ---- W1 fragments (h-part only, K=512), hi/lo ----
    for (int i = tid; i < 2048; i += NTHR) {
        int fr = i >> 5, l = i & 31;
        int ktg = fr >> 1, ntw = fr & 1;
        int nl = ntw * 8 + (l >> 2);
        int gcol = (nl >> 2) * 512 + n0_1 + (nl & 3);
        int k0 = ktg * 16 + 2 * (l & 3);
        const float* base = W_hh + gcol * 512;
        float w00 = base[k0], w01 = base[k0 + 1], w08 = base[k0 + 8], w09 = base[k0 + 9];
        __nv_bfloat16 h00 = __float2bfloat16(w00), h01 = __float2bfloat16(w01);
        __nv_bfloat16 h08 = __float2bfloat16(w08), h09 = __float2bfloat16(w09);
        u32 off = (u32)(fr * 256 + l * 8);
        *(u32*)(smem8 + SO_W1H + off)     = hpair(h00, h01);
        *(u32*)(smem8 + SO_W1H + off + 4) = hpair(h08, h09);
        *(u32*)(smem8 + SO_W1L + off)     = hpair(__float2bfloat16(w00 - __bfloat162float(h00)),
                                                  __float2bfloat16(w01 - __bfloat162float(h01)));
        *(u32*)(smem8 + SO_W1L + off + 4) = hpair(__float2bfloat16(w08 - __bfloat162float(h08)),
                                                  __float2bfloat16(w09 - __bfloat162float(h09)));
    }
    {   // W2 fragments
        const float* Wg = isH ? W_hg : W_cg;
        for (int i = tid; i < 2048; i += NTHR) {
            int fr = i >> 5, l = i & 31;
            int ktg = fr >> 1, ntw = fr & 1;
            int nl = ntw * 8 + (l >> 2);
            int pcol = (nl < 8) ? (n0_2 + nl) : (512 + n0_2 + (nl - 8));
            int k0 = ktg * 16 + 2 * (l & 3);
            float w00 = Wg[k0 * 1024 + pcol],       w01 = Wg[(k0 + 1) * 1024 + pcol];
            float w08 = Wg[(k0 + 8) * 1024 + pcol], w09 = Wg[(k0 + 9) * 1024 + pcol];
            __nv_bfloat16 h00 = __float2bfloat16(w00), h01 = __float2bfloat16(w01);
            __nv_bfloat16 h08 = __float2bfloat16(w08), h09 = __float2bfloat16(w09);
            u32 off = (u32)(fr * 256 + l * 8);
            *(u32*)(smem8 + SO_W2H + off)     = hpair(h00, h01);
            *(u32*)(smem8 + SO_W2H + off + 4) = hpair(h08, h09);
            *(u32*)(smem8 + SO_W2L + off)     = hpair(__float2bfloat16(w00 - __bfloat162float(h00)),
                                                      __float2bfloat16(w01 - __bfloat162float(h01)));
            *(u32*)(smem8 + SO_W2L + off + 4) = hpair(__float2bfloat16(w08 - __bfloat162float(h08)),
                                                      __float2bfloat16(w09 - __bfloat162float(h09)));
        }
    }
    if (tid < 16) {
        int gcol = (tid >> 2) * 512 + n0_1 + (tid & 3);
        sB1[tid] = b_ih[gcol] + b_hh[gcol];
    }

    // ---- t=0: z=0 -> mu=1e-6, std=ln2 (parity-0 buffers) ----
    if (tid < 256) {
        const float LN2 = 0.693147180559945309f;
        int i = cb * 256 + tid;       // b*512+n over grid
        int b = i >> 9, n = i & 511;
        float hs = fmaf(eps_h[i], LN2, 1e-6f);
        float cs = fmaf(eps_c[i], LN2, 1e-6f);
        __nv_bfloat16 hh = __float2bfloat16(hs);
        g_hh[i] = hh;
        g_hl[i] = __float2bfloat16(hs - __bfloat162float(hh));
        g_cs[i] = cs;
        size_t o = (size_t)b * 262656 + n;
        out[O_HMU  + o] = 1e-6f;
        out[O_HSTD + o] = LN2;
        out[O_CMU  + o] = 1e-6f;
        out[O_CSTD + o] = LN2;
    }
    grid_bar(gen);
    const int base1 = *(volatile int*)&g_cnt1[0];   // monotonic counter base (replay-safe)

    const float* epsP = isH ? eps_h : eps_c;
    const size_t muB = isH ? O_HMU  : O_CMU;
    const size_t sdB = isH ? O_HSTD : O_CSTD;
    const size_t tB  = isH ? O_HT   : O_CT;
    const __nv_bfloat16* s2H = isH ? g_nhh : g_nch;
    const __nv_bfloat16* s2L = isH ? g_nhl : g_ncl;

    const int e_b  = tid & 63;
    const int e_nn = (tid >> 6) & 3;
    const int e2_j = tid & 7;
    const int e2_b = tid >> 3;
    const int myChunk = cb >> 5;      // stage-1 output chunk this CTA feeds

    // per-step parity pointers (updated each iteration, captured by ref)
    const __nv_bfloat16 *hbufH = g_hh, *hbufL = g_hl;
    const float *cbuf = g_cs;
    __nv_bfloat16 *hbufHn, *hbufLn;
    float *cbufn;

    auto issueHL = [&](const __nv_bfloat16* H, const __nv_bfloat16* L, int bf) {
        u32 d = sbA + (u32)(bf * ABUF) + (u32)(lrow * AST) + lq32;
        const char* gh = (const char*)H + lq32;
        const char* gl = (const char*)L + lq32;
        cpa16(d,              gh);
        cpa16(d + 16,         gh + 16);
        cpa16(d + 17408,      gl);
        cpa16(d + 17408 + 16, gl + 16);
        cpa_commit();
    };
    auto issue1 = [&](int c, int bf) {
        size_t o = (size_t)lrow * 512 + (size_t)c * 128;
        issueHL(hbufH + o, hbufL + o, bf);
    };
    auto issue2 = [&](int c, int bf) {
        size_t o = (size_t)lrow * 512 + (size_t)c * 128;
        issueHL(s2H + o, s2L + o, bf);
    };

    int tgt1 = base1;                  // updated per step
    auto wait1 = [&](int c) {
        if (lane == 0) while (*(volatile int*)&g_cnt1[c] - tgt1 < 0) { }
        __syncwarp();
    };

    float acc[16];
    auto compute = [&](int bf, u32 wH, u32 wL, int ktgBase) {
        u32 ab = sbA + (u32)(bf * ABUF) + aRow + aColH + (u32)(khalf * 64);
        #pragma unroll
        for (int kt = 0; kt < 2; ++kt) {
            u32 ah[4], al[4];
            ldm4(ah, ab + kt * 32);
            ldm4(al, ab + kt * 32 + 17408);
            u32 wb = (u32)((ktgBase + kt) * 512 + lane * 8);
            u32 h0a, h0b, h1a, h1b, l0a, l0b, l1a, l1b;
            lds2(h0a, h0b, wH + wb);
            lds2(h1a, h1b, wH + wb + 256);
            lds2(l0a, l0b, wL + wb);
            lds2(l1a, l1b, wL + wb + 256);
            float* A0 = acc + kt * 8;
            float* A1 = A0 + 4;
            mma16816(A0, ah, h0a, h0b);
            mma16816(A1, ah, h1a, h1b);
            mma16816(A0, ah, l0a, l0b);
            mma16816(A1, ah, l1a, l1b);
            mma16816(A0, al, h0a, h0b);
            mma16816(A1, al, h1a, h1b);
        }
    };
    auto storeDp = [&]() {
        int rlo = mt * 16 + (lane >> 2);
        int cc  = 2 * (lane & 3);
        float* dp = Dp + khalf * 1152;
        #pragma unroll
        for (int nt = 0; nt < 2; ++nt) {
            float* A = acc + nt * 4;
            int c = nt * 8 + cc;
            dp[rlo * 18 + c]           = A[0] + A[8];
            dp[rlo * 18 + c + 1]       = A[1] + A[9];
            dp[(rlo + 8) * 18 + c]     = A[2] + A[10];
            dp[(rlo + 8) * 18 + c + 1] = A[3] + A[11];
        }
    };

    for (int s = 0; s < Sn; ++s) {
        const int p  = s & 1;
        const int pn = p ^ 1;
        hbufH = g_hh + p * BH;  hbufL = g_hl + p * BH;  cbuf = g_cs + p * BH;
        hbufHn = g_hh + pn * BH; hbufLn = g_hl + pn * BH; cbufn = g_cs + pn * BH;
        tgt1 = base1 + (s + 1) * 32;

        // ================= stage 1 (h-GEMM, 4 chunks of K=128) =================
        #pragma unroll
        for (int i = 0; i < 16; ++i) acc[i] = 0.f;
        issue1(0, 0);
        issue1(1, 1);
        float x1r[4] = {0.f, 0.f, 0.f, 0.f};
        float cold_pre = 0.f;
        if (tid < 256) {
            cold_pre = __ldcg(&cbuf[e_b * 512 + n0_1 + e_nn]);
            const float* xp = g_x1 + ((size_t)s * 128 + cb) * 1024 + e_nn * 64 + e_b;
            x1r[0] = __ldcg(xp);
            x1r[1] = __ldcg(xp + 256);
            x1r[2] = __ldcg(xp + 512);
            x1r[3] = __ldcg(xp + 768);
        }
        #pragma unroll
        for (int c = 0; c < 4; ++c) {
            if (c < 3) cpa_wait<1>(); else cpa_wait<0>();
            __syncthreads();
            compute(c % 3, sb + SO_W1H, sb + SO_W1L, c * 8 + khalf * 2);
            if (c + 2 < 4) issue1(c + 2, (c + 2) % 3);
        }
        storeDp();
        __syncthreads();
        if (tid < 256) {
            float gv[4];
            #pragma unroll
            for (int gg = 0; gg < 4; ++gg) {
                int c = gg * 4 + e_nn;
                float v = sB1[c] + x1r[gg];
                #pragma unroll
                for (int kp = 0; kp < 4; ++kp) v += Dp[kp * 1152 + e_b * 18 + c];
                gv[gg] = v;
            }
            int n = n0_1 + e_nn;
            float cv = sigm(gv[1]) * cold_pre + sigm(gv[0]) * tanhf(gv[2]);
            float hv = sigm(gv[3]) * tanhf(cv);
            __nv_bfloat16 ch = __float2bfloat16(cv);
            g_nch[e_b * 512 + n] = ch;
            g_ncl[e_b * 512 + n] = __float2bfloat16(cv - __bfloat162float(ch));
            __nv_bfloat16 hh2 = __float2bfloat16(hv);
            g_nhh[e_b * 512 + n] = hh2;
            g_nhl[e_b * 512 + n] = __float2bfloat16(hv - __bfloat162float(hh2));
        }
        __syncthreads();
        if (tid == 0) {                     // publish my chunk's columns
            __threadfence();
            atomicAdd(&g_cnt1[myChunk], 1);
        }

        // ================= stage 2 (sample GEMM, 4 chunks; dataflow waits) =====
        #pragma unroll
        for (int i = 0; i < 16; ++i) acc[i] = 0.f;
        wait1(0); issue2(0, 0);
        wait1(1); issue2(1, 1);
        float eps_pre = __ldcg(&epsP[(size_t)(s + 1) * BH + (size_t)e2_b * 512 + n0_2 + e2_j]);
        #pragma unroll
        for (int c = 0; c < 4; ++c) {
            if (c < 3) cpa_wait<1>(); else cpa_wait<0>();
            __syncthreads();
            compute(c % 3, sb + SO_W2H, sb + SO_W2L, c * 8 + khalf * 2);
            if (c + 2 < 4) { wait1(c + 2); issue2(c + 2, (c + 2) % 3); }
        }
        storeDp();
        __syncthreads();
        {   // sample epilogue: one (b, n) per thread; writes to parity-pn buffers
            int b = e2_b;
            float pm = 0.f, ps = 0.f;
            #pragma unroll
            for (int kp = 0; kp < 4; ++kp) {
                pm += Dp[kp * 1152 + b * 18 + e2_j];
                ps += Dp[kp * 1152 + b * 18 + 8 + e2_j];
            }
            float mu = fminf(fmaxf(pm, 1e-6f), 1e6f);
            float sd = fmaxf(softplus(ps), 1e-6f);
            int n = n0_2 + e2_j;
            float smp = fmaf(eps_pre, sd, mu);
            size_t o = (size_t)b * 262656 + (size_t)(s + 1) * 512 + n;
            out[muB + o] = mu;
            out[sdB + o] = sd;
            if (isH) {
                out[O_HID + (size_t)b * 262144 + (size_t)s * 512 + n] = smp;
                __nv_bfloat16 hh2 = __float2bfloat16(smp);
                hbufHn[b * 512 + n] = hh2;
                hbufLn[b * 512 + n] = __float2bfloat16(smp - __bfloat162float(hh2));
            } else {
                cbufn[b * 512 + n] = smp;
            }
            if (s == Sn - 1) out[tB + (size_t)b * 512 + n] = smp;
        }
        grid_bar(gen);                     // single end-of-step barrier
    }
}

extern "C" void kernel_launch(void* const* d_in, const int* in_sizes, int n_in,
                              void* d_out, int out_size) {
    (void)in_sizes; (void)n_in; (void)out_size;
    const float* x    = (const float*)d_in[0];
    const float* W_ih = (const float*)d_in[1];
    const float* W_hh = (const float*)d_in[2];
    const float* b_ih = (const float*)d_in[3];
    const float* b_hh = (const float*)d_in[4];
    const float* W_hg = (const float*)d_in[5];
    const float* W_cg = (const float*)d_in[6];
    const float* eps_h = (const float*)d_in[7];
    const float* eps_c = (const float*)d_in[8];
    float* out = (float*)d_out;

    xsplit_kernel<<<65536, 256>>>(x);

    cudaFuncSetAttribute(precomp, cudaFuncAttributeMaxDynamicSharedMemorySize, SMEM_P);
    precomp<<<dim3(128, 8), 512, SMEM_P>>>(W_ih);

    cudaFuncSetAttribute(rglstm, cudaFuncAttributeMaxDynamicSharedMemorySize, SMEM_BYTES);
    rglstm<<<NBLK, NTHR, SMEM_BYTES>>>(W_ih, W_hh, b_ih, b_hh,
                                       W_hg, W_cg, eps_h, eps_c, out);
}

// round 16
// speedup vs baseline: 1.0419x; 1.0419x over previous
#include <cuda_runtime.h>
#include <cuda_bf16.h>
#include <math.h>

#define NBLK 64
#define NTHR 512
#define Bn 64
#define Sn 512
#define BH 32768

typedef unsigned u32;
typedef unsigned long long u64;

// output section offsets (floats)
#define O_HID   0ull
#define O_HMU   16777216ull
#define O_HSTD  33587200ull
#define O_CMU   50397184ull
#define O_CSTD  67207168ull
#define O_HT    84017152ull
#define O_CT    84049920ull

// global state
__device__ __nv_bfloat16 g_xh[(size_t)Bn*Sn*512];   // [b][s][k]
__device__ __nv_bfloat16 g_xl[(size_t)Bn*Sn*512];
__device__ __nv_bfloat16 g_hh[2*BH], g_hl[2*BH];    // sampled h, parity-buffered
__device__ float g_cs[2*BH];                        // sampled c, parity-buffered
__device__ __nv_bfloat16 g_nhh[BH], g_nhl[BH];      // h_new
__device__ __nv_bfloat16 g_nch[BH], g_ncl[BH];      // c_new
__device__ float g_x1[(size_t)Sn*64*2048];          // precomputed x-gates [s][cb][32c][64b]
__device__ int g_flag[NBLK*32];
__device__ int g_rel;

// flag-array grid barrier over 64 CTAs, replay-safe
__device__ __forceinline__ void grid_bar(int& gen) {
    __syncthreads();
    ++gen;
    if (threadIdx.x == 0) {
        __threadfence();
        *(volatile int*)&g_flag[blockIdx.x * 32] = gen;
    }
    if (blockIdx.x == 0) {
        if (threadIdx.x < NBLK)
            while (*(volatile int*)&g_flag[threadIdx.x * 32] < gen) { }
        __syncthreads();
        if (threadIdx.x == 0) { __threadfence(); *(volatile int*)&g_rel = gen; }
    }
    if (threadIdx.x == 0) {
        while (*(volatile int*)&g_rel < gen) { }
        __threadfence();
    }
    __syncthreads();
}

__device__ __forceinline__ float sigm(float v) { return 1.0f / (1.0f + expf(-v)); }
__device__ __forceinline__ float softplus(float v) {
    return fmaxf(v, 0.0f) + log1pf(expf(-fabsf(v)));
}

// ---------- PTX helpers (sm_80+, legal on compute_100) ----------
__device__ __forceinline__ u32 smem_u32(const void* p) {
    u32 a;
    asm("{ .reg .u64 t; cvta.to.shared.u64 t, %1; cvt.u32.u64 %0, t; }" : "=r"(a) : "l"(p));
    return a;
}
__device__ __forceinline__ void cpa16(u32 dst, const void* src) {
    asm volatile("cp.async.cg.shared.global [%0], [%1], 16;" :: "r"(dst), "l"(src));
}
__device__ __forceinline__ void cpa_commit() {
    asm volatile("cp.async.commit_group;" ::: "memory");
}
template <int N> __device__ __forceinline__ void cpa_wait() {
    asm volatile("cp.async.wait_group %0;" :: "n"(N) : "memory");
}
__device__ __forceinline__ void ldm4(u32* r, u32 addr) {
    asm volatile("ldmatrix.sync.aligned.m8n8.x4.shared.b16 {%0,%1,%2,%3}, [%4];"
                 : "=r"(r[0]), "=r"(r[1]), "=r"(r[2]), "=r"(r[3]) : "r"(addr));
}
__device__ __forceinline__ void lds2(u32& x, u32& y, u32 a) {
    asm volatile("ld.shared.v2.b32 {%0,%1}, [%2];" : "=r"(x), "=r"(y) : "r"(a));
}
__device__ __forceinline__ void mma16816(float* d, const u32* a, u32 b0, u32 b1) {
    asm volatile(
        "mma.sync.aligned.m16n8k16.row.col.f32.bf16.bf16.f32 "
        "{%0,%1,%2,%3}, {%4,%5,%6,%7}, {%8,%9}, {%0,%1,%2,%3};"
        : "+f"(d[0]), "+f"(d[1]), "+f"(d[2]), "+f"(d[3])
        : "r"(a[0]), "r"(a[1]), "r"(a[2]), "r"(a[3]), "r"(b0), "r"(b1));
}
__device__ __forceinline__ u32 hpair(__nv_bfloat16 a, __nv_bfloat16 b) {
    unsigned short ua = *(unsigned short*)&a, ub = *(unsigned short*)&b;
    return (u32)ua | ((u32)ub << 16);
}

#define ABUF 34816      // per buffer: hi [64][272B] + lo at +17408
#define AST  272

// main-kernel SMEM map (bytes): W1 128 frags hi/lo, W2 128 frags hi/lo
#define SO_W1H  0
#define SO_W1L  32768
#define SO_W2H  65536
#define SO_W2L  98304
#define SO_A    131072     // 2 x 34816; Dp ALIASES buffer 0
#define SO_B1   200704
#define SMEM_BYTES 200960

// precomp-kernel SMEM map
#define SP_WXH  0
#define SP_WXL  32768
#define SP_A    65536      // 3 x 34816
#define SP_DP   169984
#define SMEM_P  204800

// one-time x split
__global__ void xsplit_kernel(const float* __restrict__ x) {
    size_t i = (size_t)blockIdx.x * 256 + threadIdx.x;
    float v = x[i];
    __nv_bfloat16 hi = __float2bfloat16(v);
    g_xh[i] = hi;
    g_xl[i] = __float2bfloat16(v - __bfloat162float(hi));
}

// ---------------- precompute: X1[s][cb] = x_s @ W_ih^T (32 cols per cb) ----------------
__global__ __launch_bounds__(512, 1)
void precomp(const float* __restrict__ W_ih) {
    extern __shared__ char smem8[];
    float* Dp = (float*)(smem8 + SP_DP);      // [4][64][34]

    const int tid  = threadIdx.x;
    const int wid  = tid >> 5;
    const int lane = tid & 31;
    const int cb   = blockIdx.x;              // 0..63
    const int sblk = blockIdx.y;              // 0..7
    const int n0_1 = cb << 3;

    const u32 sb  = smem_u32(smem8);
    const u32 sbA = sb + SP_A;

    const int mt    = wid & 3;
    const int khalf = wid >> 2;
    const u32 aRow  = (u32)((mt * 16 + (lane & 7) + ((lane >> 3) & 1) * 8) * AST);
    const u32 aColH = (u32)(((lane >> 4) & 1) * 16);
    const int lrow  = tid >> 3;
    const u32 lq32  = (u32)((tid & 7) << 5);

    // W_ih fragments: 128 frags (32 ktg x 4 nt)
    for (int i = tid; i < 4096; i += 512) {
        int fr = i >> 5, l = i & 31;
        int ktg = fr >> 2, nt = fr & 3;
        int gcol = nt * 512 + n0_1 + (l >> 2);
        int k0 = ktg * 16 + 2 * (l & 3);
        const float* base = W_ih + gcol * 512;
        float w00 = base[k0], w01 = base[k0 + 1], w08 = base[k0 + 8], w09 = base[k0 + 9];
        __nv_bfloat16 h00 = __float2bfloat16(w00), h01 = __float2bfloat16(w01);
        __nv_bfloat16 h08 = __float2bfloat16(w08), h09 = __float2bfloat16(w09);
        u32 off = (u32)(fr * 256 + l * 8);
        *(u32*)(smem8 + SP_WXH + off)     = hpair(h00, h01);
        *(u32*)(smem8 + SP_WXH + off + 4) = hpair(h08, h09);
        *(u32*)(smem8 + SP_WXL + off)     = hpair(__float2bfloat16(w00 - __bfloat162float(h00)),
                                                  __float2bfloat16(w01 - __bfloat162float(h01)));
        *(u32*)(smem8 + SP_WXL + off + 4) = hpair(__float2bfloat16(w08 - __bfloat162float(h08)),
                                                  __float2bfloat16(w09 - __bfloat162float(h09)));
    }
    __syncthreads();

    auto issueP = [&](int gc) {
        int s_ = sblk * 64 + (gc >> 2);
        int c_ = gc & 3;
        size_t o = ((size_t)lrow * Sn + s_) * 512 + (size_t)c_ * 128;
        u32 d = sbA + (u32)((gc % 3) * ABUF) + (u32)(lrow * AST) + lq32;
        const char* gh = (const char*)(g_xh + o) + lq32;
        const char* gl = (const char*)(g_xl + o) + lq32;
        cpa16(d,              gh);
        cpa16(d + 16,         gh + 16);
        cpa16(d + 17408,      gl);
        cpa16(d + 17408 + 16, gl + 16);
        cpa_commit();
    };

    float acc[32];
    auto compute = [&](int bf, u32 wH, u32 wL, int ktgBase) {
        u32 ab = sbA + (u32)(bf * ABUF) + aRow + aColH + (u32)(khalf * 64);
        #pragma unroll
        for (int kt = 0; kt < 2; ++kt) {
            u32 ah[4], al[4];
            ldm4(ah, ab + kt * 32);
            ldm4(al, ab + kt * 32 + 17408);
            int ktg = ktgBase + kt;
            #pragma unroll
            for (int nt = 0; nt < 4; ++nt) {
                u32 wb = (u32)((ktg * 4 + nt) * 256 + lane * 8);
                u32 ha, hb2, la, lb2;
                lds2(ha, hb2, wH + wb);
                lds2(la, lb2, wL + wb);
                float* A = acc + kt * 16 + nt * 4;
                mma16816(A, ah, ha, hb2);
                mma16816(A, ah, la, lb2);
                mma16816(A, al, ha, hb2);
            }
        }
    };
    auto storeDp = [&]() {
        int rlo = mt * 16 + (lane >> 2);
        int cc  = 2 * (lane & 3);
        float* dp = Dp + khalf * 2176;
        #pragma unroll
        for (int nt = 0; nt < 4; ++nt) {
            float* A = acc + nt * 4;
            int c = nt * 8 + cc;
            dp[rlo * 34 + c]           = A[0] + A[16];
            dp[rlo * 34 + c + 1]       = A[1] + A[17];
            dp[(rlo + 8) * 34 + c]     = A[2] + A[18];
            dp[(rlo + 8) * 34 + c + 1] = A[3] + A[19];
        }
    };

    const int e_nn = tid & 7;
    const int e_b  = tid >> 3;

    issueP(0); issueP(1);
    for (int sl = 0; sl < 64; ++sl) {
        #pragma unroll
        for (int i = 0; i < 32; ++i) acc[i] = 0.f;
        #pragma unroll
        for (int c = 0; c < 4; ++c) {
            int gc = sl * 4 + c;
            if (gc == 255) cpa_wait<0>(); else cpa_wait<1>();
            __syncthreads();
            compute(gc % 3, sb + SP_WXH, sb + SP_WXL, c * 8 + khalf * 2);
            if (gc + 2 < 256) issueP(gc + 2);
        }
        storeDp();
        __syncthreads();
        {
            int s_ = sblk * 64 + sl;
            float* dst = g_x1 + ((size_t)s_ * 64 + cb) * 2048;
            #pragma unroll
            for (int g = 0; g < 4; ++g) {
                int c2 = g * 8 + e_nn;
                float v = 0.f;
                #pragma unroll
                for (int kp = 0; kp < 4; ++kp) v += Dp[kp * 2176 + e_b * 34 + c2];
                dst[c2 * 64 + e_b] = v;
            }
        }
        __syncthreads();
    }
}

// ---------------- main persistent kernel (64 CTAs) ----------------
__global__ __launch_bounds__(NTHR, 1)
void rglstm(const float* __restrict__ W_ih, const float* __restrict__ W_hh,
            const float* __restrict__ b_ih, const float* __restrict__ b_hh,
            const float* __restrict__ W_hg, const float* __restrict__ W_cg,
            const float* __restrict__ eps_h, const float* __restrict__ eps_c,
            float* __restrict__ out)
{
    extern __shared__ char smem8[];
    float* sB1 = (float*)(smem8 + SO_B1);
    float* Dp  = (float*)(smem8 + SO_A);      // ALIASES A buffer 0

    const int tid  = threadIdx.x;
    const int wid  = tid >> 5;
    const int lane = tid & 31;
    const int cb   = blockIdx.x;              // 0..63
    const bool isH = cb < 32;
    const int n0_1 = cb << 3;                 // 8 hidden cols (stage 1)
    const int n0_2 = (cb & 31) << 4;          // 16 hidden cols (stage 2)

    const u32 sb  = smem_u32(smem8);
    const u32 sbA = sb + SO_A;

    const int mt    = wid & 3;
    const int khalf = wid >> 2;
    const u32 aRow  = (u32)((mt * 16 + (lane & 7) + ((lane >> 3) & 1) * 8) * AST);
    const u32 aColH = (u32)(((lane >> 4) & 1) * 16);
    const int lrow  = tid >> 3;
    const u32 lq32  = (u32)((tid & 7) << 5);

    int gen = *(volatile int*)&g_rel;         // replay-safe seed

    // ---- W1 fragments (W_hh only, K=512): 128 frags (32 ktg x 4 nt = gates) ----
    for (int i = tid; i < 4096; i += NTHR) {
        int fr = i >> 5, l = i & 31;
        int ktg = fr >> 2, nt = fr & 3;
        int gcol = nt * 512 + n0_1 + (l >> 2);
        int k0 = ktg * 16 + 2 * (l & 3);
        const float* base = W_hh + gcol * 512;
        float w00 = base[k0], w01 = base[k0 + 1], w08 = base[k0 + 8], w09 = base[k0 + 9];
        __nv_bfloat16 h00 = __float2bfloat16(w00), h01 = __float2bfloat16(w01);
        __nv_bfloat16 h08 = __float2bfloat16(w08), h09 = __float2bfloat16(w09);
        u32 off = (u32)(fr * 256 + l * 8);
        *(u32*)(smem8 + SO_W1H + off)     = hpair(h00, h01);
        *(u32*)(smem8 + SO_W1H + off + 4) = hpair(h08, h09);
        *(u32*)(smem8 + SO_W1L + off)     = hpair(__float2bfloat16(w00 - __bfloat162float(h00)),
                                                  __float2bfloat16(w01 - __bfloat162float(h01)));
        *(u32*)(smem8 + SO_W1L + off + 4) = hpair(__float2bfloat16(w08 - __bfloat162float(h08)),
                                                  __float2bfloat16(w09 - __bfloat162float(h09)));
    }
    {   // W2 fragments: 128 frags; cols 0-15 = mu, 16-31 = std
        const float* Wg = isH ? W_hg : W_cg;
        for (int i = tid; i < 4096; i += NTHR) {
            int fr = i >> 5, l = i & 31;
            int ktg = fr >> 2, nt = fr & 3;
            int c2 = nt * 8 + (l >> 2);
            int pcol = (c2 < 16) ? (n0_2 + c2) : (512 + n0_2 + (c2 - 16));
            int k0 = ktg * 16 + 2 * (l & 3);
            float w00 = Wg[k0 * 1024 + pcol],       w01 = Wg[(k0 + 1) * 1024 + pcol];
            float w08 = Wg[(k0 + 8) * 1024 + pcol], w09 = Wg[(k0 + 9) * 1024 + pcol];
            __nv_bfloat16 h00 = __float2bfloat16(w00), h01 = __float2bfloat16(w01);
            __nv_bfloat16 h08 = __float2bfloat16(w08), h09 = __float2bfloat16(w09);
            u32 off = (u32)(fr * 256 + l * 8);
            *(u32*)(smem8 + SO_W2H + off)     = hpair(h00, h01);
            *(u32*)(smem8 + SO_W2H + off + 4) = hpair(h08, h09);
            *(u32*)(smem8 + SO_W2L + off)     = hpair(__float2bfloat16(w00 - __bfloat162float(h00)),
                                                      __float2bfloat16(w01 - __bfloat162float(h01)));
            *(u32*)(smem8 + SO_W2L + off + 4) = hpair(__float2bfloat16(w08 - __bfloat162float(h08)),
                                                      __float2bfloat16(w09 - __bfloat162float(h09)));
        }
    }
    if (tid < 32) {
        int gcol = (tid >> 3) * 512 + n0_1 + (tid & 7);
        sB1[tid] = b_ih[gcol] + b_hh[gcol];
    }

    // ---- t=0: parity-0 buffers ----
    {
        const float LN2 = 0.693147180559945309f;
        int i = cb * NTHR + tid;      // 0..32767 = b*512+n
        int b = i >> 9, n = i & 511;
        float hs = fmaf(eps_h[i], LN2, 1e-6f);
        float cs = fmaf(eps_c[i], LN2, 1e-6f);
        __nv_bfloat16 hh = __float2bfloat16(hs);
        g_hh[i] = hh;
        g_hl[i] = __float2bfloat16(hs - __bfloat162float(hh));
        g_cs[i] = cs;
        size_t o = (size_t)b * 262656 + n;
        out[O_HMU  + o] = 1e-6f;
        out[O_HSTD + o] = LN2;
        out[O_CMU  + o] = 1e-6f;
        out[O_CSTD + o] = LN2;
    }
    grid_bar(gen);

    const float* epsP = isH ? eps_h : eps_c;
    const size_t muB = isH ? O_HMU  : O_CMU;
    const size_t sdB = isH ? O_HSTD : O_CSTD;
    const size_t tB  = isH ? O_HT   : O_CT;
    const __nv_bfloat16* s2H = isH ? g_nhh : g_nch;
    const __nv_bfloat16* s2L = isH ? g_nhl : g_ncl;

    const int e_nn = tid & 7;         // stage-1 epilogue: one (b, nn) per thread
    const int e_b  = tid >> 3;
    const int e2_j = tid & 15;        // stage-2 epilogue: (j, b2) x2 halves
    const int e2_b = tid >> 4;        // 0..31

    const __nv_bfloat16 *hbufH = g_hh, *hbufL = g_hl;
    const float *cbuf = g_cs;
    __nv_bfloat16 *hbufHn, *hbufLn;
    float *cbufn;

    auto issueHL = [&](const __nv_bfloat16* H, const __nv_bfloat16* L, int bf) {
        u32 d = sbA + (u32)(bf * ABUF) + (u32)(lrow * AST) + lq32;
        const char* gh = (const char*)H + lq32;
        const char* gl = (const char*)L + lq32;
        cpa16(d,              gh);
        cpa16(d + 16,         gh + 16);
        cpa16(d + 17408,      gl);
        cpa16(d + 17408 + 16, gl + 16);
        cpa_commit();
    };
    auto issue1 = [&](int c, int bf) {
        size_t o = (size_t)lrow * 512 + (size_t)c * 128;
        issueHL(hbufH + o, hbufL + o, bf);
    };
    auto issue2 = [&](int c, int bf) {
        size_t o = (size_t)lrow * 512 + (size_t)c * 128;
        issueHL(s2H + o, s2L + o, bf);
    };

    float acc[32];
    auto compute = [&](int bf, u32 wH, u32 wL, int ktgBase) {
        u32 ab = sbA + (u32)(bf * ABUF) + aRow + aColH + (u32)(khalf * 64);
        #pragma unroll
        for (int kt = 0; kt < 2; ++kt) {
            u32 ah[4], al[4];
            ldm4(ah, ab + kt * 32);
            ldm4(al, ab + kt * 32 + 17408);
            int ktg = ktgBase + kt;
            #pragma unroll
            for (int nt = 0; nt < 4; ++nt) {
                u32 wb = (u32)((ktg * 4 + nt) * 256 + lane * 8);
                u32 ha, hb2, la, lb2;
                lds2(ha, hb2, wH + wb);
                lds2(la, lb2, wL + wb);
                float* A = acc + kt * 16 + nt * 4;
                mma16816(A, ah, ha, hb2);
                mma16816(A, ah, la, lb2);
                mma16816(A, al, ha, hb2);
            }
        }
    };
    auto storeDp = [&]() {
        int rlo = mt * 16 + (lane >> 2);
        int cc  = 2 * (lane & 3);
        float* dp = Dp + khalf * 2176;
        #pragma unroll
        for (int nt = 0; nt < 4; ++nt) {
            float* A = acc + nt * 4;
            int c = nt * 8 + cc;
            dp[rlo * 34 + c]           = A[0] + A[16];
            dp[rlo * 34 + c + 1]       = A[1] + A[17];
            dp[(rlo + 8) * 34 + c]     = A[2] + A[18];
            dp[(rlo + 8) * 34 + c + 1] = A[3] + A[19];
        }
    };

    for (int s = 0; s < Sn; ++s) {
        const int p  = s & 1;
        const int pn = p ^ 1;
        hbufH = g_hh + p * BH;  hbufL = g_hl + p * BH;  cbuf = g_cs + p * BH;
        hbufHn = g_hh + pn * BH; hbufLn = g_hl + pn * BH; cbufn = g_cs + pn * BH;

        // ================= stage 1 (h-GEMM, 4 chunks of K=128) =================
        #pragma unroll
        for (int i = 0; i < 32; ++i) acc[i] = 0.f;
        issue1(0, 0);
        issue1(1, 1);
        float x1r[4];
        float cold_pre = __ldcg(&cbuf[e_b * 512 + n0_1 + e_nn]);
        {
            const float* xp = g_x1 + ((size_t)s * 64 + cb) * 2048 + e_nn * 64 + e_b;
            x1r[0] = __ldcg(xp);
            x1r[1] = __ldcg(xp + 512);
            x1r[2] = __ldcg(xp + 1024);
            x1r[3] = __ldcg(xp + 1536);
        }
        #pragma unroll
        for (int c = 0; c < 4; ++c) {
            if (c < 3) cpa_wait<1>(); else cpa_wait<0>();
            __syncthreads();
            compute(c & 1, sb + SO_W1H, sb + SO_W1L, c * 8 + khalf * 2);
            if (c + 2 < 4) { __syncthreads(); issue1(c + 2, c & 1); }
        }
        storeDp();
        __syncthreads();
        {   // LSTM pointwise: one (b, nn) per thread
            float gv[4];
            #pragma unroll
            for (int g = 0; g < 4; ++g) {
                int c = g * 8 + e_nn;
                float v = sB1[c] + x1r[g];
                #pragma unroll
                for (int kp = 0; kp < 4; ++kp) v += Dp[kp * 2176 + e_b * 34 + c];
                gv[g] = v;
            }
            int n = n0_1 + e_nn;
            float cv = sigm(gv[1]) * cold_pre + sigm(gv[0]) * tanhf(gv[2]);
            float hv = sigm(gv[3]) * tanhf(cv);
            __nv_bfloat16 ch = __float2bfloat16(cv);
            g_nch[e_b * 512 + n] = ch;
            g_ncl[e_b * 512 + n] = __float2bfloat16(cv - __bfloat162float(ch));
            __nv_bfloat16 hh2 = __float2bfloat16(hv);
            g_nhh[e_b * 512 + n] = hh2;
            g_nhl[e_b * 512 + n] = __float2bfloat16(hv - __bfloat162float(hh2));
        }
        grid_bar(gen);

        // ================= stage 2 (sample GEMM, 4 chunks of K=128) =================
        #pragma unroll
        for (int i = 0; i < 32; ++i) acc[i] = 0.f;
        issue2(0, 0);
        issue2(1, 1);
        float eps0 = __ldcg(&epsP[(size_t)(s + 1) * BH + (size_t)e2_b * 512 + n0_2 + e2_j]);
        float eps1 = __ldcg(&epsP[(size_t)(s + 1) * BH + (size_t)(e2_b + 32) * 512 + n0_2 + e2_j]);
        #pragma unroll
        for (int c = 0; c < 4; ++c) {
            if (c < 3) cpa_wait<1>(); else cpa_wait<0>();
            __syncthreads();
            compute(c & 1, sb + SO_W2H, sb + SO_W2L, c * 8 + khalf * 2);
            if (c + 2 < 4) { __syncthreads(); issue2(c + 2, c & 1); }
        }
        storeDp();
        __syncthreads();
        #pragma unroll
        for (int half = 0; half < 2; ++half) {
            int b = e2_b + half * 32;
            float ep = half ? eps1 : eps0;
            float pm = 0.f, ps = 0.f;
            #pragma unroll
            for (int kp = 0; kp < 4; ++kp) {
                pm += Dp[kp * 2176 + b * 34 + e2_j];
                ps += Dp[kp * 2176 + b * 34 + 16 + e2_j];
            }
            float mu = fminf(fmaxf(pm, 1e-6f), 1e6f);
            float sd = fmaxf(softplus(ps), 1e-6f);
            int n = n0_2 + e2_j;
            float smp = fmaf(ep, sd, mu);
            size_t o = (size_t)b * 262656 + (size_t)(s + 1) * 512 + n;
            out[muB + o] = mu;
            out[sdB + o] = sd;
            if (isH) {
                out[O_HID + (size_t)b * 262144 + (size_t)s * 512 + n] = smp;
                __nv_bfloat16 hh2 = __float2bfloat16(smp);
                hbufHn[b * 512 + n] = hh2;
                hbufLn[b * 512 + n] = __float2bfloat16(smp - __bfloat162float(hh2));
            } else {
                cbufn[b * 512 + n] = smp;
            }
            if (s == Sn - 1) out[tB + (size_t)b * 512 + n] = smp;
        }
        grid_bar(gen);
    }
}

extern "C" void kernel_launch(void* const* d_in, const int* in_sizes, int n_in,
                              void* d_out, int out_size) {
    (void)in_sizes; (void)n_in; (void)out_size;
    const float* x    = (const float*)d_in[0];
    const float* W_ih = (const float*)d_in[1];
    const float* W_hh = (const float*)d_in[2];
    const float* b_ih = (const float*)d_in[3];
    const float* b_hh = (const float*)d_in[4];
    const float* W_hg = (const float*)d_in[5];
    const float* W_cg = (const float*)d_in[6];
    const float* eps_h = (const float*)d_in[7];
    const float* eps_c = (const float*)d_in[8];
    float* out = (float*)d_out;

    xsplit_kernel<<<65536, 256>>>(x);

    cudaFuncSetAttribute(precomp, cudaFuncAttributeMaxDynamicSharedMemorySize, SMEM_P);
    precomp<<<dim3(64, 8), 512, SMEM_P>>>(W_ih);

    cudaFuncSetAttribute(rglstm, cudaFuncAttributeMaxDynamicSharedMemorySize, SMEM_BYTES);
    rglstm<<<NBLK, NTHR, SMEM_BYTES>>>(W_ih, W_hh, b_ih, b_hh,
                                       W_hg, W_cg, eps_h, eps_c, out);
}